// round 10
// baseline (speedup 1.0000x reference)
#include <cuda_runtime.h>

// MaskRCNN RPN, single-launch: stream blocks (scores/boxes/anchors) +
// label blocks (768 labels each, block-level GT culling, guard-band IoU).

#define B_   2
#define A_   20
#define NTOT 261888

#define OUT_SC 0
#define OUT_BX (B_ * NTOT * 2)
#define OUT_AN (OUT_BX + B_ * NTOT * 4)
#define OUT_LB (OUT_AN + B_ * NTOT * 4)

#define STREAM_BLOCKS 1023
#define LABEL_BLOCKS  682          // 523776 / 768
#define LB_CHUNK      768

struct LvlPtrs {
    const float* cs[5];
    const float* bp[5];
};

__device__ __forceinline__ void get_level(int n, int& lvl, int& offv) {
    if      (n < 196608) { lvl = 0; offv = 0;      }
    else if (n < 245760) { lvl = 1; offv = 196608; }
    else if (n < 258048) { lvl = 2; offv = 245760; }
    else if (n < 261120) { lvl = 3; offv = 258048; }
    else                 { lvl = 4; offv = 261120; }
}

__global__ void __launch_bounds__(256)
rpn_fused_kernel(LvlPtrs p,
                 const float* __restrict__ gt,   // B*A*4
                 const int* __restrict__ gtc,    // B (int32 as delivered)
                 float* __restrict__ out)
{
    int tx = threadIdx.x;

    if (blockIdx.x < STREAM_BLOCKS) {
        // ---------------- stream role: scores / boxes / anchors ----------------
        int t = blockIdx.x * 256 + tx;
        int gid = t * 2;
        if (gid >= B_ * NTOT) return;

        int b = (gid >= NTOT) ? 1 : 0;
        int n = gid - b * NTOT;

        int lvl, offv;
        get_level(n, lvl, offv);

        int log2w  = 8 - lvl;
        int log2hw = 2 * log2w;
        int hw     = 1 << log2hw;

        int local = n - offv;
        int a   = local >> log2hw;
        int rem = local & (hw - 1);
        int y   = rem >> log2w;
        int x0  = rem & ((1 << log2w) - 1);

        float s    = (float)(1 << (lvl + 2));
        float half = 0.5f * (s - 1.0f);
        float base = (float)(1 << (lvl + 6));
        float cy  = s * (float)y + half;
        float cx0 = s * (float)x0 + half;
        float hh = (a == 2) ? 2.0f * base : base;
        float ww = (a == 0) ? 2.0f * base : base;

        const float* csp = p.cs[lvl];
        const float* bpp = p.bp[lvl];
        int cbase = (b * 6  + a * 2) * hw + rem;
        int bbase = (b * 12 + a * 4) * hw + rem;

        float2 c0 = *reinterpret_cast<const float2*>(csp + cbase);
        float2 c1 = *reinterpret_cast<const float2*>(csp + cbase + hw);
        float2 dy = *reinterpret_cast<const float2*>(bpp + bbase);
        float2 dx = *reinterpret_cast<const float2*>(bpp + bbase + hw);
        float2 dh = *reinterpret_cast<const float2*>(bpp + bbase + 2 * hw);
        float2 dw = *reinterpret_cast<const float2*>(bpp + bbase + 3 * hw);

        long long row = (long long)b * NTOT + n;

        *reinterpret_cast<float4*>(out + OUT_SC + row * 2) =
            make_float4(c0.x, c1.x, c0.y, c1.y);

        float dyv[2] = {dy.x, dy.y};
        float dxv[2] = {dx.x, dx.y};
        float dhv[2] = {dh.x, dh.y};
        float dwv[2] = {dw.x, dw.y};

        float4* bx = reinterpret_cast<float4*>(out + OUT_BX + row * 4);
        float4* an = reinterpret_cast<float4*>(out + OUT_AN + row * 4);

#pragma unroll
        for (int j = 0; j < 2; ++j) {
            float cxj = cx0 + (float)j * s;
            float cyc = cy  + dyv[j] * hh;
            float cxc = cxj + dxv[j] * ww;
            float h2  = hh * __expf(dhv[j]);
            float w2  = ww * __expf(dwv[j]);
            bx[j] = make_float4(cyc - 0.5f * h2, cxc - 0.5f * w2,
                                cyc + 0.5f * h2, cxc + 0.5f * w2);
            an[j] = make_float4(cy, cxj, hh, ww);
        }
        return;
    }

    // ---------------- label role: 768 labels per block ----------------
    __shared__ float4 s_gb[A_];
    __shared__ float  s_sga[A_];
    __shared__ int    s_ns;

    int lb   = blockIdx.x - STREAM_BLOCKS;
    int gidL = lb * LB_CHUNK;                 // global anchor index of chunk start
    int b    = (gidL >= NTOT) ? 1 : 0;        // chunk never crosses batch (768 | NTOT)
    int n0   = gidL - b * NTOT;

    int lvl, offv;
    get_level(n0, lvl, offv);                 // chunk never crosses level (768 | sizes)

    int log2w  = 8 - lvl;
    int log2hw = 2 * log2w;
    int hw     = 1 << log2hw;
    int w      = 1 << log2w;
    int local0 = n0 - offv;

    float s    = (float)(1 << (lvl + 2));
    float half = 0.5f * (s - 1.0f);
    float base = (float)(1 << (lvl + 6));
    float area1 = base * base;                // anchor areas are area1 or 2*area1

    // block y-range (conservative: full range if chunk spans anchor types)
    int a0 = local0 >> log2hw;
    int a1 = (local0 + LB_CHUNK - 1) >> log2hw;
    int yblk_lo, yblk_hi;
    if (a0 != a1) { yblk_lo = 0; yblk_hi = w - 1; }
    else {
        yblk_lo = (local0 & (hw - 1)) >> log2w;
        yblk_hi = ((local0 + LB_CHUNK - 1) & (hw - 1)) >> log2w;
    }

    if (tx == 0) s_ns = 0;
    __syncthreads();

    if (tx < A_) {
        int cnt = gtc[b];
        cnt = (cnt < 0) ? 0 : (cnt > A_ ? A_ : cnt);
        if (tx < cnt) {
            float4 gb = reinterpret_cast<const float4*>(gt)[b * A_ + tx];
            float gh = __fsub_rn(gb.z, gb.x);
            float gw = __fsub_rn(gb.w, gb.y);
            float ga = __fmul_rn(gh, gw);
            // size-compat for either anchor area (conservative)
            bool okA = 3.0f * fminf(area1, ga)        >= 0.999f * (area1 + ga);
            bool okB = 3.0f * fminf(2.0f * area1, ga) >= 0.999f * (2.0f * area1 + ga);
            bool survive = okA || okB;
            if (survive) {
                // y-range overlap (anchor box must touch GT; hh_max = 2*base)
                float lo = gb.x - base - half;        // cy >= gy1 - hh_max/2
                float hi = gb.z + base - half;        // cy <= gy2 + hh_max/2
                int gylo = (int)floorf(lo / s) - 1;
                int gyhi = (int)ceilf (hi / s) + 1;
                if (gyhi < yblk_lo || gylo > yblk_hi) survive = false;
            }
            if (survive) {
                int slot = atomicAdd(&s_ns, 1);
                s_gb[slot]  = gb;
                s_sga[slot] = ga;
            }
        }
    }
    __syncthreads();

    int ns = s_ns;
    const float KT = 1.0f / 3.0f;

#pragma unroll
    for (int j = 0; j < 3; ++j) {
        int local = local0 + tx + j * 256;
        int a   = local >> log2hw;
        int rem = local & (hw - 1);
        int y   = rem >> log2w;
        int x   = rem & (w - 1);

        float lab = 0.0f;
        if (ns > 0) {
            float cy = s * (float)y + half;
            float cx = s * (float)x + half;
            float hh = (a == 2) ? 2.0f * base : base;
            float ww = (a == 0) ? 2.0f * base : base;
            float hh2 = 0.5f * hh, ww2 = 0.5f * ww;
            float ay1 = __fsub_rn(cy, hh2);
            float ay2 = __fadd_rn(ay1, hh);
            float ax1 = __fsub_rn(cx, ww2);
            float ax2 = __fadd_rn(ax1, ww);
            float area = __fmul_rn(hh, ww);

            for (int k = 0; k < ns; ++k) {
                float4 gb = s_gb[k];
                float ga  = s_sga[k];
                float thr = __fadd_rn(area, ga);

                float yy1 = fminf(fmaxf(ay1, gb.x), gb.z);
                float yy2 = fminf(fmaxf(ay2, gb.x), gb.z);
                float xx1 = fminf(fmaxf(ax1, gb.y), gb.w);
                float xx2 = fminf(fmaxf(ax2, gb.y), gb.w);
                float inter = __fmul_rn(__fsub_rn(yy2, yy1), __fsub_rn(xx2, xx1));

                float kthr = thr * KT;
                if (inter >= kthr * 1.00002f) { lab = 1.0f; break; }
                if (inter >= kthr * 0.99998f) {
                    // ambiguous band: exact reference-equivalent decision
                    float uni = __fsub_rn(thr, inter);
                    const double Cd = 0.5 - 0x1p-26;
                    if ((double)inter >= Cd * (double)uni) { lab = 1.0f; break; }
                }
            }
        }
        out[OUT_LB + b * NTOT + offv + local] = lab;
    }
}

extern "C" void kernel_launch(void* const* d_in, const int* in_sizes, int n_in,
                              void* d_out, int out_size)
{
    LvlPtrs p;
    const float* gt = nullptr;
    const int* gtc = nullptr;
    const int cs_sz[5] = {786432, 196608, 49152, 12288, 3072};
    const int bp_sz[5] = {1572864, 393216, 98304, 24576, 6144};

    for (int k = 0; k < n_in; ++k) {
        int sz = in_sizes[k];
        bool matched = false;
        for (int l = 0; l < 5 && !matched; ++l) {
            if (sz == cs_sz[l]) { p.cs[l] = (const float*)d_in[k]; matched = true; }
            else if (sz == bp_sz[l]) { p.bp[l] = (const float*)d_in[k]; matched = true; }
        }
        if (!matched) {
            if (sz == B_ * A_ * 4) gt = (const float*)d_in[k];
            else if (sz == B_)     gtc = (const int*)d_in[k];
        }
    }

    float* out = (float*)d_out;
    rpn_fused_kernel<<<STREAM_BLOCKS + LABEL_BLOCKS, 256>>>(p, gt, gtc, out);
}

// round 11
// speedup vs baseline: 1.8125x; 1.8125x over previous
#include <cuda_runtime.h>

// MaskRCNN RPN, single-launch v2: label blocks first (latency hides under
// stream blocks), stream blocks do scores/boxes/anchors. NO fp64 anywhere:
// ambiguous-band labels decided by the reference's own fp32 division.

#define B_   2
#define A_   20
#define NTOT 261888

#define OUT_SC 0
#define OUT_BX (B_ * NTOT * 2)
#define OUT_AN (OUT_BX + B_ * NTOT * 4)
#define OUT_LB (OUT_AN + B_ * NTOT * 4)

#define LABEL_BLOCKS  682          // 523776 / 768
#define STREAM_BLOCKS 1023
#define LB_CHUNK      768

struct LvlPtrs {
    const float* cs[5];
    const float* bp[5];
};

__device__ __forceinline__ void get_level(int n, int& lvl, int& offv) {
    if      (n < 196608) { lvl = 0; offv = 0;      }
    else if (n < 245760) { lvl = 1; offv = 196608; }
    else if (n < 258048) { lvl = 2; offv = 245760; }
    else if (n < 261120) { lvl = 3; offv = 258048; }
    else                 { lvl = 4; offv = 261120; }
}

__global__ void __launch_bounds__(256)
rpn_fused_kernel(LvlPtrs p,
                 const float* __restrict__ gt,   // B*A*4
                 const int* __restrict__ gtc,    // B (int32 as delivered)
                 float* __restrict__ out)
{
    int tx = threadIdx.x;

    if (blockIdx.x >= LABEL_BLOCKS) {
        // ---------------- stream role: scores / boxes / anchors ----------------
        int t = (blockIdx.x - LABEL_BLOCKS) * 256 + tx;
        int gid = t * 2;
        if (gid >= B_ * NTOT) return;

        int b = (gid >= NTOT) ? 1 : 0;
        int n = gid - b * NTOT;

        int lvl, offv;
        get_level(n, lvl, offv);

        int log2w  = 8 - lvl;
        int log2hw = 2 * log2w;
        int hw     = 1 << log2hw;

        int local = n - offv;
        int a   = local >> log2hw;
        int rem = local & (hw - 1);
        int y   = rem >> log2w;
        int x0  = rem & ((1 << log2w) - 1);

        float s    = (float)(1 << (lvl + 2));
        float half = 0.5f * (s - 1.0f);
        float base = (float)(1 << (lvl + 6));
        float cy  = s * (float)y + half;
        float cx0 = s * (float)x0 + half;
        float hh = (a == 2) ? 2.0f * base : base;
        float ww = (a == 0) ? 2.0f * base : base;

        const float* csp = p.cs[lvl];
        const float* bpp = p.bp[lvl];
        int cbase = (b * 6  + a * 2) * hw + rem;
        int bbase = (b * 12 + a * 4) * hw + rem;

        float2 c0 = *reinterpret_cast<const float2*>(csp + cbase);
        float2 c1 = *reinterpret_cast<const float2*>(csp + cbase + hw);
        float2 dy = *reinterpret_cast<const float2*>(bpp + bbase);
        float2 dx = *reinterpret_cast<const float2*>(bpp + bbase + hw);
        float2 dh = *reinterpret_cast<const float2*>(bpp + bbase + 2 * hw);
        float2 dw = *reinterpret_cast<const float2*>(bpp + bbase + 3 * hw);

        long long row = (long long)b * NTOT + n;

        *reinterpret_cast<float4*>(out + OUT_SC + row * 2) =
            make_float4(c0.x, c1.x, c0.y, c1.y);

        float dyv[2] = {dy.x, dy.y};
        float dxv[2] = {dx.x, dx.y};
        float dhv[2] = {dh.x, dh.y};
        float dwv[2] = {dw.x, dw.y};

        float4* bx = reinterpret_cast<float4*>(out + OUT_BX + row * 4);
        float4* an = reinterpret_cast<float4*>(out + OUT_AN + row * 4);

#pragma unroll
        for (int j = 0; j < 2; ++j) {
            float cxj = cx0 + (float)j * s;
            float cyc = cy  + dyv[j] * hh;
            float cxc = cxj + dxv[j] * ww;
            float h2  = hh * __expf(dhv[j]);
            float w2  = ww * __expf(dwv[j]);
            bx[j] = make_float4(cyc - 0.5f * h2, cxc - 0.5f * w2,
                                cyc + 0.5f * h2, cxc + 0.5f * w2);
            an[j] = make_float4(cy, cxj, hh, ww);
        }
        return;
    }

    // ---------------- label role: 768 labels per block ----------------
    __shared__ float4 s_gb[A_];
    __shared__ float  s_sga[A_];
    __shared__ int    s_ns;

    int lb   = blockIdx.x;
    int gidL = lb * LB_CHUNK;                 // chunk never crosses batch/level
    int b    = (gidL >= NTOT) ? 1 : 0;
    int n0   = gidL - b * NTOT;

    int lvl, offv;
    get_level(n0, lvl, offv);

    int log2w  = 8 - lvl;
    int log2hw = 2 * log2w;
    int hw     = 1 << log2hw;
    int w      = 1 << log2w;
    int local0 = n0 - offv;

    float s    = (float)(1 << (lvl + 2));
    float half = 0.5f * (s - 1.0f);
    float base = (float)(1 << (lvl + 6));
    float area1 = base * base;

    int a0 = local0 >> log2hw;
    int a1 = (local0 + LB_CHUNK - 1) >> log2hw;
    int yblk_lo, yblk_hi;
    if (a0 != a1) { yblk_lo = 0; yblk_hi = w - 1; }
    else {
        yblk_lo = (local0 & (hw - 1)) >> log2w;
        yblk_hi = ((local0 + LB_CHUNK - 1) & (hw - 1)) >> log2w;
    }

    if (tx == 0) s_ns = 0;
    __syncthreads();

    if (tx < A_) {
        // independent loads: issue both, one DRAM/L2 round-trip
        float4 gb = reinterpret_cast<const float4*>(gt)[b * A_ + tx];
        int cnt = gtc[b];
        cnt = (cnt < 0) ? 0 : (cnt > A_ ? A_ : cnt);
        if (tx < cnt) {
            float gh = __fsub_rn(gb.z, gb.x);
            float gw = __fsub_rn(gb.w, gb.y);
            float ga = __fmul_rn(gh, gw);
            bool okA = 3.0f * fminf(area1, ga)        >= 0.999f * (area1 + ga);
            bool okB = 3.0f * fminf(2.0f * area1, ga) >= 0.999f * (2.0f * area1 + ga);
            bool survive = okA || okB;
            if (survive) {
                float lo = gb.x - base - half;
                float hi = gb.z + base - half;
                int gylo = (int)floorf(lo / s) - 1;
                int gyhi = (int)ceilf (hi / s) + 1;
                if (gyhi < yblk_lo || gylo > yblk_hi) survive = false;
            }
            if (survive) {
                int slot = atomicAdd(&s_ns, 1);
                s_gb[slot]  = gb;
                s_sga[slot] = ga;
            }
        }
    }
    __syncthreads();

    int ns = s_ns;
    const float KT = 1.0f / 3.0f;

#pragma unroll
    for (int j = 0; j < 3; ++j) {
        int local = local0 + tx + j * 256;
        int a   = local >> log2hw;
        int rem = local & (hw - 1);
        int y   = rem >> log2w;
        int x   = rem & (w - 1);

        float lab = 0.0f;
        if (ns > 0) {
            float cy = s * (float)y + half;
            float cx = s * (float)x + half;
            float hh = (a == 2) ? 2.0f * base : base;
            float ww = (a == 0) ? 2.0f * base : base;
            float hh2 = 0.5f * hh, ww2 = 0.5f * ww;
            float ay1 = __fsub_rn(cy, hh2);
            float ay2 = __fadd_rn(ay1, hh);
            float ax1 = __fsub_rn(cx, ww2);
            float ax2 = __fadd_rn(ax1, ww);
            float area = __fmul_rn(hh, ww);

            for (int k = 0; k < ns; ++k) {
                float4 gb = s_gb[k];
                float ga  = s_sga[k];
                float thr = __fadd_rn(area, ga);

                float yy1 = fminf(fmaxf(ay1, gb.x), gb.z);
                float yy2 = fminf(fmaxf(ay2, gb.x), gb.z);
                float xx1 = fminf(fmaxf(ax1, gb.y), gb.w);
                float xx2 = fminf(fmaxf(ax2, gb.y), gb.w);
                float inter = __fmul_rn(__fsub_rn(yy2, yy1), __fsub_rn(xx2, xx1));

                float kthr = thr * KT;
                if (inter >= kthr * 0.99998f) {
                    if (inter >= kthr * 1.00002f) { lab = 1.0f; break; }
                    // ambiguous band: the reference's exact fp32 division
                    float uni = __fsub_rn(thr, inter);
                    if (inter / uni >= 0.5f) { lab = 1.0f; break; }
                }
            }
        }
        out[OUT_LB + b * NTOT + offv + local] = lab;
    }
}

extern "C" void kernel_launch(void* const* d_in, const int* in_sizes, int n_in,
                              void* d_out, int out_size)
{
    LvlPtrs p;
    const float* gt = nullptr;
    const int* gtc = nullptr;
    const int cs_sz[5] = {786432, 196608, 49152, 12288, 3072};
    const int bp_sz[5] = {1572864, 393216, 98304, 24576, 6144};

    for (int k = 0; k < n_in; ++k) {
        int sz = in_sizes[k];
        bool matched = false;
        for (int l = 0; l < 5 && !matched; ++l) {
            if (sz == cs_sz[l]) { p.cs[l] = (const float*)d_in[k]; matched = true; }
            else if (sz == bp_sz[l]) { p.bp[l] = (const float*)d_in[k]; matched = true; }
        }
        if (!matched) {
            if (sz == B_ * A_ * 4) gt = (const float*)d_in[k];
            else if (sz == B_)     gtc = (const int*)d_in[k];
        }
    }

    float* out = (float*)d_out;
    rpn_fused_kernel<<<LABEL_BLOCKS + STREAM_BLOCKS, 256>>>(p, gt, gtc, out);
}

// round 12
// speedup vs baseline: 2.3057x; 1.2721x over previous
#include <cuda_runtime.h>

// MaskRCNN RPN, single-launch v3: stream blocks (scores/boxes/anchors) +
// label blocks (zero-fill own 768-label chunk, then GT-centric scatter of
// positives restricted to the chunk). No fp64. Race-free by ownership.

#define B_   2
#define A_   20
#define NTOT 261888

#define OUT_SC 0
#define OUT_BX (B_ * NTOT * 2)
#define OUT_AN (OUT_BX + B_ * NTOT * 4)
#define OUT_LB (OUT_AN + B_ * NTOT * 4)

#define LABEL_BLOCKS  682          // 523776 / 768
#define STREAM_BLOCKS 1023
#define LB_CHUNK      768

struct LvlPtrs {
    const float* cs[5];
    const float* bp[5];
};

__device__ __forceinline__ void get_level(int n, int& lvl, int& offv) {
    if      (n < 196608) { lvl = 0; offv = 0;      }
    else if (n < 245760) { lvl = 1; offv = 196608; }
    else if (n < 258048) { lvl = 2; offv = 245760; }
    else if (n < 261120) { lvl = 3; offv = 258048; }
    else                 { lvl = 4; offv = 261120; }
}

__global__ void __launch_bounds__(256)
rpn_fused_kernel(LvlPtrs p,
                 const float* __restrict__ gt,   // B*A*4
                 const int* __restrict__ gtc,    // B (int32 as delivered)
                 float* __restrict__ out)
{
    int tx = threadIdx.x;

    if (blockIdx.x >= LABEL_BLOCKS) {
        // ---------------- stream role: scores / boxes / anchors ----------------
        int t = (blockIdx.x - LABEL_BLOCKS) * 256 + tx;
        int gid = t * 2;
        if (gid >= B_ * NTOT) return;

        int b = (gid >= NTOT) ? 1 : 0;
        int n = gid - b * NTOT;

        int lvl, offv;
        get_level(n, lvl, offv);

        int log2w  = 8 - lvl;
        int log2hw = 2 * log2w;
        int hw     = 1 << log2hw;

        int local = n - offv;
        int a   = local >> log2hw;
        int rem = local & (hw - 1);
        int y   = rem >> log2w;
        int x0  = rem & ((1 << log2w) - 1);

        float s    = (float)(1 << (lvl + 2));
        float half = 0.5f * (s - 1.0f);
        float base = (float)(1 << (lvl + 6));
        float cy  = s * (float)y + half;
        float cx0 = s * (float)x0 + half;
        float hh = (a == 2) ? 2.0f * base : base;
        float ww = (a == 0) ? 2.0f * base : base;

        const float* csp = p.cs[lvl];
        const float* bpp = p.bp[lvl];
        int cbase = (b * 6  + a * 2) * hw + rem;
        int bbase = (b * 12 + a * 4) * hw + rem;

        float2 c0 = *reinterpret_cast<const float2*>(csp + cbase);
        float2 c1 = *reinterpret_cast<const float2*>(csp + cbase + hw);
        float2 dy = *reinterpret_cast<const float2*>(bpp + bbase);
        float2 dx = *reinterpret_cast<const float2*>(bpp + bbase + hw);
        float2 dh = *reinterpret_cast<const float2*>(bpp + bbase + 2 * hw);
        float2 dw = *reinterpret_cast<const float2*>(bpp + bbase + 3 * hw);

        long long row = (long long)b * NTOT + n;

        *reinterpret_cast<float4*>(out + OUT_SC + row * 2) =
            make_float4(c0.x, c1.x, c0.y, c1.y);

        float dyv[2] = {dy.x, dy.y};
        float dxv[2] = {dx.x, dx.y};
        float dhv[2] = {dh.x, dh.y};
        float dwv[2] = {dw.x, dw.y};

        float4* bx = reinterpret_cast<float4*>(out + OUT_BX + row * 4);
        float4* an = reinterpret_cast<float4*>(out + OUT_AN + row * 4);

#pragma unroll
        for (int j = 0; j < 2; ++j) {
            float cxj = cx0 + (float)j * s;
            float cyc = cy  + dyv[j] * hh;
            float cxc = cxj + dxv[j] * ww;
            float h2  = hh * __expf(dhv[j]);
            float w2  = ww * __expf(dwv[j]);
            bx[j] = make_float4(cyc - 0.5f * h2, cxc - 0.5f * w2,
                                cyc + 0.5f * h2, cxc + 0.5f * w2);
            an[j] = make_float4(cy, cxj, hh, ww);
        }
        return;
    }

    // ---------------- label role: own 768-label chunk ----------------
    __shared__ float4 s_gb[A_];
    __shared__ float  s_sga[A_];
    __shared__ int    s_ns;

    int lb   = blockIdx.x;
    int gidL = lb * LB_CHUNK;                 // chunk never crosses batch; whole rows
    int b    = (gidL >= NTOT) ? 1 : 0;
    int n0   = gidL - b * NTOT;

    int lvl, offv;
    get_level(n0, lvl, offv);                 // chunk never crosses level

    int log2w  = 8 - lvl;
    int log2hw = 2 * log2w;
    int hw     = 1 << log2hw;
    int w      = 1 << log2w;
    int local0 = n0 - offv;

    float s    = (float)(1 << (lvl + 2));
    float half = 0.5f * (s - 1.0f);
    float base = (float)(1 << (lvl + 6));
    float area1 = base * base;

    // zero-fill chunk (vectorized; base 3072B-aligned)
    float4* zp = reinterpret_cast<float4*>(out + OUT_LB + b * NTOT + n0);
    if (tx < LB_CHUNK / 4) zp[tx] = make_float4(0.f, 0.f, 0.f, 0.f);

    if (tx == 0) s_ns = 0;
    __syncthreads();

    if (tx < A_) {
        float4 gb = reinterpret_cast<const float4*>(gt)[b * A_ + tx];
        int cnt = gtc[b];
        cnt = (cnt < 0) ? 0 : (cnt > A_ ? A_ : cnt);
        if (tx < cnt) {
            float gh = __fsub_rn(gb.z, gb.x);
            float gw = __fsub_rn(gb.w, gb.y);
            float ga = __fmul_rn(gh, gw);
            bool okA = 3.0f * fminf(area1, ga)        >= 0.999f * (area1 + ga);
            bool okB = 3.0f * fminf(2.0f * area1, ga) >= 0.999f * (2.0f * area1 + ga);
            if (okA || okB) {
                int slot = atomicAdd(&s_ns, 1);
                s_gb[slot]  = gb;
                s_sga[slot] = ga;
            }
        }
    }
    __syncthreads();                          // zeros visible + survivors ready

    int ns = s_ns;
    int a_first = local0 >> log2hw;
    int a_last  = (local0 + LB_CHUNK - 1) >> log2hw;

    for (int k = 0; k < ns; ++k) {
        float4 gb = s_gb[k];
        float ga  = s_sga[k];
        float gh  = __fsub_rn(gb.z, gb.x);
        float gw  = __fsub_rn(gb.w, gb.y);

        for (int a = a_first; a <= a_last; ++a) {
            float hh = (a == 2) ? 2.0f * base : base;
            float ww = (a == 0) ? 2.0f * base : base;
            float area = __fmul_rn(hh, ww);
            float thr  = __fadd_rn(area, ga);
            float req  = thr * (1.0f / 3.0f) * 0.9999f;
            if (fminf(area, ga) < req) continue;

            float hh2 = 0.5f * hh, ww2 = 0.5f * ww;
            float oy_max = fminf(hh, gh);
            float ox_max = fminf(ww, gw);
            float oy_req = (req / ox_max) * 0.9999f;
            float ox_req = (req / oy_max) * 0.9999f;

            int ylo = (int)floorf((gb.x + oy_req - hh2 - half) / s) - 1;
            int yhi = (int)ceilf ((gb.z - oy_req + hh2 - half) / s) + 1;
            int xlo = (int)floorf((gb.y + ox_req - ww2 - half) / s) - 1;
            int xhi = (int)ceilf ((gb.w - ox_req + ww2 - half) / s) + 1;
            xlo = max(xlo, 0); xhi = min(xhi, w - 1);

            // intersect y with this chunk's rows for anchor-type a
            int i_lo = max(local0, a << log2hw);
            int i_hi = min(local0 + LB_CHUNK, (a + 1) << log2hw);
            int cy_lo = (i_lo - (a << log2hw)) >> log2w;
            int cy_hi = (i_hi - 1 - (a << log2hw)) >> log2w;
            ylo = max(ylo, cy_lo); yhi = min(yhi, cy_hi);
            if (ylo > yhi || xlo > xhi) continue;

            int nx = xhi - xlo + 1;
            int ncand = (yhi - ylo + 1) * nx;

            float kthr = thr * (1.0f / 3.0f);
            float m_hi = kthr * 1.00002f;
            float m_lo = kthr * 0.99998f;
            int abase = OUT_LB + b * NTOT + offv + (a << log2hw);

            for (int idx = tx; idx < ncand; idx += 256) {
                int yy = idx / nx;
                int xx = idx - yy * nx;
                int y = ylo + yy;
                int x = xlo + xx;

                float cy  = s * (float)y + half;
                float cx  = s * (float)x + half;
                float ay1 = __fsub_rn(cy, hh2);
                float ay2 = __fadd_rn(ay1, hh);
                float ax1 = __fsub_rn(cx, ww2);
                float ax2 = __fadd_rn(ax1, ww);

                float yy1 = fminf(fmaxf(ay1, gb.x), gb.z);
                float yy2 = fminf(fmaxf(ay2, gb.x), gb.z);
                float xx1 = fminf(fmaxf(ax1, gb.y), gb.w);
                float xx2 = fminf(fmaxf(ax2, gb.y), gb.w);
                float inter = __fmul_rn(__fsub_rn(yy2, yy1), __fsub_rn(xx2, xx1));

                bool pos = false;
                if (inter >= m_hi)      pos = true;
                else if (inter >= m_lo) {
                    // ambiguous band: the reference's own fp32 division
                    float uni = __fsub_rn(thr, inter);
                    pos = (inter / uni >= 0.5f);
                }
                if (pos) out[abase + (y << log2w) + x] = 1.0f;
            }
        }
    }
}

extern "C" void kernel_launch(void* const* d_in, const int* in_sizes, int n_in,
                              void* d_out, int out_size)
{
    LvlPtrs p;
    const float* gt = nullptr;
    const int* gtc = nullptr;
    const int cs_sz[5] = {786432, 196608, 49152, 12288, 3072};
    const int bp_sz[5] = {1572864, 393216, 98304, 24576, 6144};

    for (int k = 0; k < n_in; ++k) {
        int sz = in_sizes[k];
        bool matched = false;
        for (int l = 0; l < 5 && !matched; ++l) {
            if (sz == cs_sz[l]) { p.cs[l] = (const float*)d_in[k]; matched = true; }
            else if (sz == bp_sz[l]) { p.bp[l] = (const float*)d_in[k]; matched = true; }
        }
        if (!matched) {
            if (sz == B_ * A_ * 4) gt = (const float*)d_in[k];
            else if (sz == B_)     gtc = (const int*)d_in[k];
        }
    }

    float* out = (float*)d_out;
    rpn_fused_kernel<<<LABEL_BLOCKS + STREAM_BLOCKS, 256>>>(p, gt, gtc, out);
}

// round 13
// speedup vs baseline: 2.4763x; 1.0740x over previous
#include <cuda_runtime.h>

// MaskRCNN RPN, single-launch v4: v3 + register cap (256,8) for full occupancy
// + int32 output indexing. Stream blocks: scores/boxes/anchors. Label blocks:
// zero-fill own 768-label chunk then GT-centric scatter. No fp64.

#define B_   2
#define A_   20
#define NTOT 261888

#define OUT_SC 0
#define OUT_BX (B_ * NTOT * 2)
#define OUT_AN (OUT_BX + B_ * NTOT * 4)
#define OUT_LB (OUT_AN + B_ * NTOT * 4)

#define LABEL_BLOCKS  682          // 523776 / 768
#define STREAM_BLOCKS 1023
#define LB_CHUNK      768

struct LvlPtrs {
    const float* cs[5];
    const float* bp[5];
};

__device__ __forceinline__ void get_level(int n, int& lvl, int& offv) {
    if      (n < 196608) { lvl = 0; offv = 0;      }
    else if (n < 245760) { lvl = 1; offv = 196608; }
    else if (n < 258048) { lvl = 2; offv = 245760; }
    else if (n < 261120) { lvl = 3; offv = 258048; }
    else                 { lvl = 4; offv = 261120; }
}

__global__ void __launch_bounds__(256, 8)
rpn_fused_kernel(LvlPtrs p,
                 const float* __restrict__ gt,   // B*A*4
                 const int* __restrict__ gtc,    // B (int32 as delivered)
                 float* __restrict__ out)
{
    int tx = threadIdx.x;

    if (blockIdx.x >= LABEL_BLOCKS) {
        // ---------------- stream role: scores / boxes / anchors ----------------
        int t = (blockIdx.x - LABEL_BLOCKS) * 256 + tx;
        int gid = t * 2;
        if (gid >= B_ * NTOT) return;

        int b = (gid >= NTOT) ? 1 : 0;
        int n = gid - b * NTOT;

        int lvl, offv;
        get_level(n, lvl, offv);

        int log2w  = 8 - lvl;
        int log2hw = 2 * log2w;
        int hw     = 1 << log2hw;

        int local = n - offv;
        int a   = local >> log2hw;
        int rem = local & (hw - 1);
        int y   = rem >> log2w;
        int x0  = rem & ((1 << log2w) - 1);

        float s    = (float)(1 << (lvl + 2));
        float half = 0.5f * (s - 1.0f);
        float base = (float)(1 << (lvl + 6));
        float cy  = s * (float)y + half;
        float cx0 = s * (float)x0 + half;
        float hh = (a == 2) ? 2.0f * base : base;
        float ww = (a == 0) ? 2.0f * base : base;

        const float* csp = p.cs[lvl];
        const float* bpp = p.bp[lvl];
        int cbase = (b * 6  + a * 2) * hw + rem;
        int bbase = (b * 12 + a * 4) * hw + rem;

        float2 c0 = *reinterpret_cast<const float2*>(csp + cbase);
        float2 c1 = *reinterpret_cast<const float2*>(csp + cbase + hw);
        float2 dy = *reinterpret_cast<const float2*>(bpp + bbase);
        float2 dx = *reinterpret_cast<const float2*>(bpp + bbase + hw);
        float2 dh = *reinterpret_cast<const float2*>(bpp + bbase + 2 * hw);
        float2 dw = *reinterpret_cast<const float2*>(bpp + bbase + 3 * hw);

        int row = b * NTOT + n;                // fits int32

        *reinterpret_cast<float4*>(out + OUT_SC + row * 2) =
            make_float4(c0.x, c1.x, c0.y, c1.y);

        float dyv[2] = {dy.x, dy.y};
        float dxv[2] = {dx.x, dx.y};
        float dhv[2] = {dh.x, dh.y};
        float dwv[2] = {dw.x, dw.y};

        float4* bx = reinterpret_cast<float4*>(out + OUT_BX + row * 4);
        float4* an = reinterpret_cast<float4*>(out + OUT_AN + row * 4);

#pragma unroll
        for (int j = 0; j < 2; ++j) {
            float cxj = cx0 + (float)j * s;
            float cyc = cy  + dyv[j] * hh;
            float cxc = cxj + dxv[j] * ww;
            float h2  = hh * __expf(dhv[j]);
            float w2  = ww * __expf(dwv[j]);
            bx[j] = make_float4(cyc - 0.5f * h2, cxc - 0.5f * w2,
                                cyc + 0.5f * h2, cxc + 0.5f * w2);
            an[j] = make_float4(cy, cxj, hh, ww);
        }
        return;
    }

    // ---------------- label role: own 768-label chunk ----------------
    __shared__ float4 s_gb[A_];
    __shared__ float  s_sga[A_];
    __shared__ int    s_ns;

    int lb   = blockIdx.x;
    int gidL = lb * LB_CHUNK;                 // chunk never crosses batch; whole rows
    int b    = (gidL >= NTOT) ? 1 : 0;
    int n0   = gidL - b * NTOT;

    int lvl, offv;
    get_level(n0, lvl, offv);                 // chunk never crosses level

    int log2w  = 8 - lvl;
    int log2hw = 2 * log2w;
    int hw     = 1 << log2hw;
    int w      = 1 << log2w;
    int local0 = n0 - offv;

    float s    = (float)(1 << (lvl + 2));
    float half = 0.5f * (s - 1.0f);
    float base = (float)(1 << (lvl + 6));
    float area1 = base * base;

    // zero-fill chunk (vectorized; base 3072B-aligned)
    float4* zp = reinterpret_cast<float4*>(out + OUT_LB + b * NTOT + n0);
    if (tx < LB_CHUNK / 4) zp[tx] = make_float4(0.f, 0.f, 0.f, 0.f);

    if (tx == 0) s_ns = 0;
    __syncthreads();

    if (tx < A_) {
        float4 gb = reinterpret_cast<const float4*>(gt)[b * A_ + tx];
        int cnt = gtc[b];
        cnt = (cnt < 0) ? 0 : (cnt > A_ ? A_ : cnt);
        if (tx < cnt) {
            float gh = __fsub_rn(gb.z, gb.x);
            float gw = __fsub_rn(gb.w, gb.y);
            float ga = __fmul_rn(gh, gw);
            bool okA = 3.0f * fminf(area1, ga)        >= 0.999f * (area1 + ga);
            bool okB = 3.0f * fminf(2.0f * area1, ga) >= 0.999f * (2.0f * area1 + ga);
            if (okA || okB) {
                int slot = atomicAdd(&s_ns, 1);
                s_gb[slot]  = gb;
                s_sga[slot] = ga;
            }
        }
    }
    __syncthreads();                          // zeros visible + survivors ready

    int ns = s_ns;
    int a_first = local0 >> log2hw;
    int a_last  = (local0 + LB_CHUNK - 1) >> log2hw;

    for (int k = 0; k < ns; ++k) {
        float4 gb = s_gb[k];
        float ga  = s_sga[k];
        float gh  = __fsub_rn(gb.z, gb.x);
        float gw  = __fsub_rn(gb.w, gb.y);

        for (int a = a_first; a <= a_last; ++a) {
            float hh = (a == 2) ? 2.0f * base : base;
            float ww = (a == 0) ? 2.0f * base : base;
            float area = __fmul_rn(hh, ww);
            float thr  = __fadd_rn(area, ga);
            float req  = thr * (1.0f / 3.0f) * 0.9999f;
            if (fminf(area, ga) < req) continue;

            float hh2 = 0.5f * hh, ww2 = 0.5f * ww;
            float oy_max = fminf(hh, gh);
            float ox_max = fminf(ww, gw);
            float oy_req = (req / ox_max) * 0.9999f;
            float ox_req = (req / oy_max) * 0.9999f;

            int ylo = (int)floorf((gb.x + oy_req - hh2 - half) / s) - 1;
            int yhi = (int)ceilf ((gb.z - oy_req + hh2 - half) / s) + 1;
            int xlo = (int)floorf((gb.y + ox_req - ww2 - half) / s) - 1;
            int xhi = (int)ceilf ((gb.w - ox_req + ww2 - half) / s) + 1;
            xlo = max(xlo, 0); xhi = min(xhi, w - 1);

            // intersect y with this chunk's rows for anchor-type a
            int i_lo = max(local0, a << log2hw);
            int i_hi = min(local0 + LB_CHUNK, (a + 1) << log2hw);
            int cy_lo = (i_lo - (a << log2hw)) >> log2w;
            int cy_hi = (i_hi - 1 - (a << log2hw)) >> log2w;
            ylo = max(ylo, cy_lo); yhi = min(yhi, cy_hi);
            if (ylo > yhi || xlo > xhi) continue;

            int nx = xhi - xlo + 1;
            int ncand = (yhi - ylo + 1) * nx;

            float kthr = thr * (1.0f / 3.0f);
            float m_hi = kthr * 1.00002f;
            float m_lo = kthr * 0.99998f;
            int abase = OUT_LB + b * NTOT + offv + (a << log2hw);

            for (int idx = tx; idx < ncand; idx += 256) {
                int yy = idx / nx;
                int xx = idx - yy * nx;
                int y = ylo + yy;
                int x = xlo + xx;

                float cy  = s * (float)y + half;
                float cx  = s * (float)x + half;
                float ay1 = __fsub_rn(cy, hh2);
                float ay2 = __fadd_rn(ay1, hh);
                float ax1 = __fsub_rn(cx, ww2);
                float ax2 = __fadd_rn(ax1, ww);

                float yy1 = fminf(fmaxf(ay1, gb.x), gb.z);
                float yy2 = fminf(fmaxf(ay2, gb.x), gb.z);
                float xx1 = fminf(fmaxf(ax1, gb.y), gb.w);
                float xx2 = fminf(fmaxf(ax2, gb.y), gb.w);
                float inter = __fmul_rn(__fsub_rn(yy2, yy1), __fsub_rn(xx2, xx1));

                bool pos = false;
                if (inter >= m_hi)      pos = true;
                else if (inter >= m_lo) {
                    // ambiguous band: the reference's own fp32 division
                    float uni = __fsub_rn(thr, inter);
                    pos = (inter / uni >= 0.5f);
                }
                if (pos) out[abase + (y << log2w) + x] = 1.0f;
            }
        }
    }
}

extern "C" void kernel_launch(void* const* d_in, const int* in_sizes, int n_in,
                              void* d_out, int out_size)
{
    LvlPtrs p;
    const float* gt = nullptr;
    const int* gtc = nullptr;
    const int cs_sz[5] = {786432, 196608, 49152, 12288, 3072};
    const int bp_sz[5] = {1572864, 393216, 98304, 24576, 6144};

    for (int k = 0; k < n_in; ++k) {
        int sz = in_sizes[k];
        bool matched = false;
        for (int l = 0; l < 5 && !matched; ++l) {
            if (sz == cs_sz[l]) { p.cs[l] = (const float*)d_in[k]; matched = true; }
            else if (sz == bp_sz[l]) { p.bp[l] = (const float*)d_in[k]; matched = true; }
        }
        if (!matched) {
            if (sz == B_ * A_ * 4) gt = (const float*)d_in[k];
            else if (sz == B_)     gtc = (const int*)d_in[k];
        }
    }

    float* out = (float*)d_out;
    rpn_fused_kernel<<<LABEL_BLOCKS + STREAM_BLOCKS, 256>>>(p, gt, gtc, out);
}